// round 2
// baseline (speedup 1.0000x reference)
#include <cuda_runtime.h>

#define EPS 1e-5f

#define BX 8
#define CCH 512
#define KCODES 32
#define NPIX 16384   // 128*128

// ---------------- device scratch (allocation-free rule -> device globals) ----
__device__ float g_feat[(size_t)BX * NPIX * CCH];   // [B][N][C]  268MB
__device__ float g_enc[BX * KCODES * CCH];          // [B][K][C]
__device__ float g_awsum[BX * KCODES];              // [B][K]
__device__ float g_encfeat[BX * CCH];               // [B][C]
__device__ float g_gamma1p[BX * CCH];               // 1 + sigmoid(...)

// ---------------- K0: zero accumulators ------------------------------------
__global__ void k_zero() {
    int i = blockIdx.x * 256 + threadIdx.x;
    if (i < BX * KCODES * CCH) g_enc[i] = 0.f;
    if (i < BX * KCODES) g_awsum[i] = 0.f;
}

// ---------------- K1: conv(1x1) + BN2 + ReLU  -> g_feat [B][N][C] -----------
// Per batch: feat[m, n] = relu(bn( sum_k X[k, m] * W[n, k] ))
// M = NPIX (pixels), Nc = 512 (cout), Kd = 512 (cin)
// Tiling: BM=128, BN=128, BK=16; 256 threads; 8x8 microtile split 4+4 (conflict-free)
__global__ __launch_bounds__(256, 2) void k_conv(
    const float* __restrict__ x, const float* __restrict__ w,
    const float* __restrict__ bg, const float* __restrict__ bb,
    const float* __restrict__ bm, const float* __restrict__ bv)
{
    __shared__ float As[16][128];
    __shared__ float Bs[16][128];

    const int b  = blockIdx.z;
    const int m0 = blockIdx.x * 128;
    const int n0 = blockIdx.y * 128;
    const int tid = threadIdx.x;
    const int tx = tid & 15;
    const int ty = tid >> 4;

    const float* xb = x + (size_t)b * CCH * NPIX;

    float acc[8][8];
#pragma unroll
    for (int i = 0; i < 8; i++)
#pragma unroll
        for (int j = 0; j < 8; j++) acc[i][j] = 0.f;

    const int arow = tid >> 4;          // kk   0..15
    const int aseg = (tid & 15) * 8;    // m    0..120
    const int bnn  = tid >> 1;          // nn   0..127
    const int bhalf = (tid & 1) * 8;    // k sub-offset

    for (int k0 = 0; k0 < CCH; k0 += 16) {
        // A tile: As[kk][m] = x[(k0+kk)*NPIX + m0+m]   (contiguous in m)
        const float4* ap = (const float4*)(xb + (size_t)(k0 + arow) * NPIX + m0 + aseg);
        float4 av0 = ap[0];
        float4 av1 = ap[1];
        *(float4*)&As[arow][aseg]     = av0;
        *(float4*)&As[arow][aseg + 4] = av1;
        // B tile: Bs[kk][nn] = w[(n0+nn)*C + k0+kk]
        const float* wp = w + (size_t)(n0 + bnn) * CCH + k0 + bhalf;
        float4 bv0 = *(const float4*)wp;
        float4 bv1 = *(const float4*)(wp + 4);
        Bs[bhalf + 0][bnn] = bv0.x; Bs[bhalf + 1][bnn] = bv0.y;
        Bs[bhalf + 2][bnn] = bv0.z; Bs[bhalf + 3][bnn] = bv0.w;
        Bs[bhalf + 4][bnn] = bv1.x; Bs[bhalf + 5][bnn] = bv1.y;
        Bs[bhalf + 6][bnn] = bv1.z; Bs[bhalf + 7][bnn] = bv1.w;
        __syncthreads();

#pragma unroll
        for (int kk = 0; kk < 16; kk++) {
            float4 al = *(const float4*)&As[kk][ty * 4];
            float4 ah = *(const float4*)&As[kk][64 + ty * 4];
            float4 bl = *(const float4*)&Bs[kk][tx * 4];
            float4 bh = *(const float4*)&Bs[kk][64 + tx * 4];
            float ar[8] = {al.x, al.y, al.z, al.w, ah.x, ah.y, ah.z, ah.w};
            float br[8] = {bl.x, bl.y, bl.z, bl.w, bh.x, bh.y, bh.z, bh.w};
#pragma unroll
            for (int i = 0; i < 8; i++)
#pragma unroll
                for (int j = 0; j < 8; j++) acc[i][j] += ar[i] * br[j];
        }
        __syncthreads();
    }

    // epilogue: BN (eval) + ReLU, store feat[(b*NPIX + m)*C + n]
    float sj[8], mj[8], tj[8];
#pragma unroll
    for (int j = 0; j < 8; j++) {
        int n = n0 + ((j < 4) ? (tx * 4 + j) : (64 + tx * 4 + j - 4));
        sj[j] = bg[n] * rsqrtf(bv[n] + EPS);
        mj[j] = bm[n];
        tj[j] = bb[n];
    }
#pragma unroll
    for (int i = 0; i < 8; i++) {
        int m = m0 + ((i < 4) ? (ty * 4 + i) : (64 + ty * 4 + i - 4));
        float* op = g_feat + ((size_t)b * NPIX + m) * CCH + n0;
        float4 v0, v1;
        v0.x = fmaxf((acc[i][0] - mj[0]) * sj[0] + tj[0], 0.f);
        v0.y = fmaxf((acc[i][1] - mj[1]) * sj[1] + tj[1], 0.f);
        v0.z = fmaxf((acc[i][2] - mj[2]) * sj[2] + tj[2], 0.f);
        v0.w = fmaxf((acc[i][3] - mj[3]) * sj[3] + tj[3], 0.f);
        v1.x = fmaxf((acc[i][4] - mj[4]) * sj[4] + tj[4], 0.f);
        v1.y = fmaxf((acc[i][5] - mj[5]) * sj[5] + tj[5], 0.f);
        v1.z = fmaxf((acc[i][6] - mj[6]) * sj[6] + tj[6], 0.f);
        v1.w = fmaxf((acc[i][7] - mj[7]) * sj[7] + tj[7], 0.f);
        *(float4*)(op + tx * 4)      = v0;
        *(float4*)(op + 64 + tx * 4) = v1;
    }
}

// ---------------- K2: scaled-L2 softmax assignment + aggregation ------------
// 512 blocks of 256 threads; each block = (b, chunk of 256 pixels).
// smem: codewords (stride 520 -> conflict-free), per-pixel feat row, softmax scratch.
#define CWS 520
__global__ __launch_bounds__(256, 2) void k_assign(
    const float* __restrict__ cw, const float* __restrict__ scale)
{
    extern __shared__ float sm[];
    float* cw_s = sm;                      // 32*520
    float* fr   = cw_s + KCODES * CWS;     // 512
    float* xc_s = fr + 512;                // 32
    float* aw_s = xc_s + 32;               // 32
    float* aws  = aw_s + 32;               // 32
    float* c2_s = aws + 32;                // 32
    float* sc_s = c2_s + 32;               // 32
    float* x2p  = sc_s + 32;               // 1

    const int tid = threadIdx.x;
    const int b   = blockIdx.x >> 6;            // 64 chunks/batch
    const int n0  = (blockIdx.x & 63) * 256;

    for (int i = tid; i < KCODES * CCH; i += 256) {
        int k = i >> 9, c = i & 511;
        cw_s[k * CWS + c] = cw[i];
    }
    if (tid < 32) { sc_s[tid] = scale[tid]; aws[tid] = 0.f; }
    __syncthreads();

    const int kq = tid >> 3;    // codeword this thread helps with
    const int cs = tid & 7;     // channel lane within the 8-thread group
    {
        float c2p = 0.f;
#pragma unroll 16
        for (int j = 0; j < 64; j++) {
            float v = cw_s[kq * CWS + cs + 8 * j];
            c2p += v * v;
        }
        c2p += __shfl_xor_sync(~0u, c2p, 4);
        c2p += __shfl_xor_sync(~0u, c2p, 2);
        c2p += __shfl_xor_sync(~0u, c2p, 1);
        if (cs == 0) c2_s[kq] = c2p;
    }

    float acc0[KCODES], acc1[KCODES];
#pragma unroll
    for (int k = 0; k < KCODES; k++) { acc0[k] = 0.f; acc1[k] = 0.f; }

    const float* fb = g_feat + ((size_t)b * NPIX + n0) * CCH;

    for (int p = 0; p < 256; p++) {
        __syncthreads();
        fr[tid]       = fb[(size_t)p * CCH + tid];
        fr[tid + 256] = fb[(size_t)p * CCH + tid + 256];
        __syncthreads();

        float dp = 0.f, p2 = 0.f;
#pragma unroll 16
        for (int j = 0; j < 64; j++) {
            float f = fr[cs + 8 * j];
            dp += f * cw_s[kq * CWS + cs + 8 * j];
            p2 += f * f;
        }
        dp += __shfl_xor_sync(~0u, dp, 4);
        dp += __shfl_xor_sync(~0u, dp, 2);
        dp += __shfl_xor_sync(~0u, dp, 1);
        p2 += __shfl_xor_sync(~0u, p2, 4);
        p2 += __shfl_xor_sync(~0u, p2, 2);
        p2 += __shfl_xor_sync(~0u, p2, 1);
        if (cs == 0) xc_s[kq] = dp;
        if (tid == 0) x2p[0] = p2;
        __syncthreads();

        if (tid < 32) {
            float l = sc_s[tid] * (x2p[0] - 2.f * xc_s[tid] + c2_s[tid]);
            float mx = l;
            mx = fmaxf(mx, __shfl_xor_sync(~0u, mx, 16));
            mx = fmaxf(mx, __shfl_xor_sync(~0u, mx, 8));
            mx = fmaxf(mx, __shfl_xor_sync(~0u, mx, 4));
            mx = fmaxf(mx, __shfl_xor_sync(~0u, mx, 2));
            mx = fmaxf(mx, __shfl_xor_sync(~0u, mx, 1));
            float e = __expf(l - mx);
            float s = e;
            s += __shfl_xor_sync(~0u, s, 16);
            s += __shfl_xor_sync(~0u, s, 8);
            s += __shfl_xor_sync(~0u, s, 4);
            s += __shfl_xor_sync(~0u, s, 2);
            s += __shfl_xor_sync(~0u, s, 1);
            float a = e / s;
            aw_s[tid] = a;
            aws[tid] += a;
        }
        __syncthreads();

        float f0 = fr[tid], f1 = fr[tid + 256];
#pragma unroll
        for (int k = 0; k < KCODES; k++) {
            float a = aw_s[k];
            acc0[k] += a * f0;
            acc1[k] += a * f1;
        }
    }

    // flush partials
    float* eb = g_enc + (size_t)b * KCODES * CCH;
#pragma unroll
    for (int k = 0; k < KCODES; k++) {
        atomicAdd(&eb[k * CCH + tid], acc0[k]);
        atomicAdd(&eb[k * CCH + tid + 256], acc1[k]);
    }
    __syncthreads();
    if (tid < 32) atomicAdd(&g_awsum[b * KCODES + tid], aws[tid]);
}

// ---------------- K3: finalize enc -> BN1 + ReLU + mean over codes ----------
__global__ void k_final(const float* __restrict__ cw,
                        const float* __restrict__ g1, const float* __restrict__ b1,
                        const float* __restrict__ m1, const float* __restrict__ v1,
                        float* __restrict__ out)
{
    int b = blockIdx.x;
    int c = threadIdx.x;     // 512 threads
    float sum = 0.f;
#pragma unroll
    for (int k = 0; k < KCODES; k++) {
        float e = g_enc[(b * KCODES + k) * CCH + c] - g_awsum[b * KCODES + k] * cw[k * CCH + c];
        float s = g1[k] * rsqrtf(v1[k] + EPS);
        e = (e - m1[k]) * s + b1[k];
        sum += fmaxf(e, 0.f);
    }
    float ef = sum * (1.f / (float)KCODES);
    g_encfeat[b * CCH + c] = ef;
    out[b * CCH + c] = ef;                 // encoding_feat output
}

// ---------------- K4: fc + sigmoid -> 1+gamma --------------------------------
__global__ void k_fc(const float* __restrict__ fcw, const float* __restrict__ fcb)
{
    int w = blockIdx.x * 8 + (threadIdx.x >> 5);   // 4096 warps total
    int lane = threadIdx.x & 31;
    int b = w >> 9, co = w & 511;
    const float* wr = fcw + (size_t)co * CCH;
    const float* ef = g_encfeat + b * CCH;
    float s = 0.f;
#pragma unroll
    for (int j = 0; j < 16; j++) s += wr[lane + 32 * j] * ef[lane + 32 * j];
    s += __shfl_xor_sync(~0u, s, 16);
    s += __shfl_xor_sync(~0u, s, 8);
    s += __shfl_xor_sync(~0u, s, 4);
    s += __shfl_xor_sync(~0u, s, 2);
    s += __shfl_xor_sync(~0u, s, 1);
    if (lane == 0)
        g_gamma1p[w] = 1.f + 1.f / (1.f + __expf(-(s + fcb[co])));
}

// ---------------- K5: output = relu(x * (1+gamma)) ---------------------------
__global__ void k_out(const float4* __restrict__ x4, float4* __restrict__ o4, int n4)
{
    int i = blockIdx.x * blockDim.x + threadIdx.x;
    if (i >= n4) return;
    float g = g_gamma1p[i >> 12];        // 4096 float4 per (b,c) plane
    float4 v = x4[i];
    v.x = fmaxf(v.x * g, 0.f);
    v.y = fmaxf(v.y * g, 0.f);
    v.z = fmaxf(v.z * g, 0.f);
    v.w = fmaxf(v.w * g, 0.f);
    o4[i] = v;
}

// ---------------- launch -----------------------------------------------------
extern "C" void kernel_launch(void* const* d_in, const int* in_sizes, int n_in,
                              void* d_out, int out_size)
{
    const float* x    = (const float*)d_in[0];
    const float* cwn  = (const float*)d_in[1];   // conv_w
    const float* b2g  = (const float*)d_in[2];
    const float* b2b  = (const float*)d_in[3];
    const float* b2m  = (const float*)d_in[4];
    const float* b2v  = (const float*)d_in[5];
    const float* cw   = (const float*)d_in[6];   // codewords
    const float* sc   = (const float*)d_in[7];   // scale
    const float* b1g  = (const float*)d_in[8];
    const float* b1b  = (const float*)d_in[9];
    const float* b1m  = (const float*)d_in[10];
    const float* b1v  = (const float*)d_in[11];
    const float* fcw  = (const float*)d_in[12];
    const float* fcb  = (const float*)d_in[13];
    float* out = (float*)d_out;

    const int assign_smem = (KCODES * CWS + 512 + 32 * 5 + 8) * 4;
    cudaFuncSetAttribute(k_assign, cudaFuncAttributeMaxDynamicSharedMemorySize,
                         assign_smem);

    k_zero<<<(BX * KCODES * CCH + 255) / 256, 256>>>();

    dim3 g1(NPIX / 128, CCH / 128, BX);
    k_conv<<<g1, 256>>>(x, cwn, b2g, b2b, b2m, b2v);

    k_assign<<<BX * (NPIX / 256), 256, assign_smem>>>(cw, sc);

    k_final<<<BX, CCH>>>(cw, b1g, b1b, b1m, b1v, out);

    k_fc<<<BX * CCH / 8, 256>>>(fcw, fcb);

    int n4 = BX * CCH * NPIX / 4;   // 16,777,216 float4
    k_out<<<n4 / 256, 256>>>((const float4*)x, (float4*)(out + BX * CCH), n4);
}

// round 4
// speedup vs baseline: 1.3303x; 1.3303x over previous
#include <cuda_runtime.h>
#include <cstdint>

#define EPS 1e-5f

#define BX 8
#define CCH 512
#define KCODES 32
#define NPIX 16384   // 128*128

// ---------------- device scratch ----------------
__device__ float g_feat[(size_t)BX * NPIX * CCH];   // [B][N][C]  268MB
__device__ float g_enc[BX * KCODES * CCH];          // [B][K][C]
__device__ float g_awsum[BX * KCODES];              // [B][K]
__device__ float g_encfeat[BX * CCH];               // [B][C]
__device__ float g_gamma1p[BX * CCH];               // 1 + sigmoid(...)

// ---------------- helpers ----------------
__device__ __forceinline__ uint32_t smem_u32(const void* p) {
    uint32_t a;
    asm("{ .reg .u64 t; cvta.to.shared.u64 t, %1; cvt.u32.u64 %0, t; }" : "=r"(a) : "l"(p));
    return a;
}
__device__ __forceinline__ unsigned tf32r(float v) {
    unsigned u; asm("cvt.rna.tf32.f32 %0, %1;" : "=r"(u) : "f"(v)); return u;
}
#define CP16(dst, src) \
    asm volatile("cp.async.cg.shared.global [%0], [%1], 16;" :: "r"(dst), "l"(src))
#define CPCOMMIT() asm volatile("cp.async.commit_group;" ::: "memory")
#define CPWAIT0()  asm volatile("cp.async.wait_group 0;" ::: "memory")

__device__ __forceinline__ void mma_tf32(float* c, const unsigned* a, const unsigned* b) {
    asm volatile("mma.sync.aligned.m16n8k8.row.col.f32.tf32.tf32.f32 "
        "{%0,%1,%2,%3}, {%4,%5,%6,%7}, {%8,%9}, {%0,%1,%2,%3};"
        : "+f"(c[0]), "+f"(c[1]), "+f"(c[2]), "+f"(c[3])
        : "r"(a[0]), "r"(a[1]), "r"(a[2]), "r"(a[3]), "r"(b[0]), "r"(b[1]));
}

// ---------------- K0: zero accumulators ----------------
__global__ void k_zero() {
    int i = blockIdx.x * 256 + threadIdx.x;
    if (i < BX * KCODES * CCH) g_enc[i] = 0.f;
    if (i < BX * KCODES) g_awsum[i] = 0.f;
}

// ---------------- K1: conv(1x1)+BN2+ReLU via mma.sync tf32 ----------------
// feat[m=pixel, n=cout] = relu(bn( sum_k x[k,m] * w[n,k] )), per batch.
// Block 128x128, BK=32, double-buffered cp.async.
// smem: As [k][m] stride 136 (transposed on epilogue? no: A loaded直接 [k][m],
//       fragments read with conflict-free bank pattern), Bs [n][k] stride 40.
#define ASTR 136
#define BSTR 40
#define ATILE (32 * ASTR)   // 4352 floats
#define BTILE (128 * BSTR)  // 5120 floats

__global__ __launch_bounds__(256, 2) void k_conv_mma(
    const float* __restrict__ x, const float* __restrict__ w,
    const float* __restrict__ bg, const float* __restrict__ bb,
    const float* __restrict__ bm, const float* __restrict__ bv)
{
    extern __shared__ float dsm[];
    // layout: A0 | A1 | B0 | B1
    float* Abuf[2] = { dsm, dsm + ATILE };
    float* Bbuf[2] = { dsm + 2 * ATILE, dsm + 2 * ATILE + BTILE };
    __shared__ float bnS[128], bnM[128], bnT[128];

    const int tid  = threadIdx.x;
    const int wid  = tid >> 5;
    const int lane = tid & 31;
    const int g    = lane >> 2;     // groupID
    const int tg   = lane & 3;      // threadID_in_group
    const int warp_m = wid >> 2;    // 0..1
    const int warp_n = wid & 3;     // 0..3

    const int b  = blockIdx.z;
    const int m0 = blockIdx.x * 128;
    const int n0 = blockIdx.y * 128;

    if (tid < 128) {
        int n = n0 + tid;
        bnS[tid] = bg[n] * rsqrtf(bv[n] + EPS);
        bnM[tid] = bm[n];
        bnT[tid] = bb[n];
    }

    const float* xb = x + (size_t)b * CCH * NPIX;

    // loader indices
    const int arow = tid >> 3;            // k-row 0..31
    const int mseg = (tid & 7) * 16;      // m 0..112
    const int bn   = tid >> 1;            // n 0..127
    const int koff = (tid & 1) * 16;      // k sub 0/16

    // prologue: tile 0 -> buf 0
    {
        const float* asrc = xb + (size_t)arow * NPIX + m0 + mseg;
        uint32_t adst = smem_u32(Abuf[0] + arow * ASTR + mseg);
#pragma unroll
        for (int j = 0; j < 4; j++) CP16(adst + j * 16, asrc + j * 4);
        const float* bsrc = w + (size_t)(n0 + bn) * CCH + koff;
        uint32_t bdst = smem_u32(Bbuf[0] + bn * BSTR + koff);
#pragma unroll
        for (int j = 0; j < 4; j++) CP16(bdst + j * 16, bsrc + j * 4);
        CPCOMMIT();
    }

    float c[4][4][4];
#pragma unroll
    for (int i = 0; i < 4; i++)
#pragma unroll
        for (int j = 0; j < 4; j++)
#pragma unroll
            for (int r = 0; r < 4; r++) c[i][j][r] = 0.f;

    for (int kt = 0; kt < 16; kt++) {
        CPWAIT0();
        __syncthreads();

        if (kt < 15) {   // prefetch next into other buffer (safe: sync above)
            int k0 = (kt + 1) * 32;
            const float* asrc = xb + (size_t)(k0 + arow) * NPIX + m0 + mseg;
            uint32_t adst = smem_u32(Abuf[(kt + 1) & 1] + arow * ASTR + mseg);
#pragma unroll
            for (int j = 0; j < 4; j++) CP16(adst + j * 16, asrc + j * 4);
            const float* bsrc = w + (size_t)(n0 + bn) * CCH + k0 + koff;
            uint32_t bdst = smem_u32(Bbuf[(kt + 1) & 1] + bn * BSTR + koff);
#pragma unroll
            for (int j = 0; j < 4; j++) CP16(bdst + j * 16, bsrc + j * 4);
            CPCOMMIT();
        }

        const float* As = Abuf[kt & 1];
        const float* Bs = Bbuf[kt & 1];
        const int mb = warp_m * 64;
        const int nb = warp_n * 32;

#pragma unroll
        for (int s = 0; s < 4; s++) {
            const int kb = s * 8;
            unsigned af[4][4];
#pragma unroll
            for (int i = 0; i < 4; i++) {
                int m = mb + i * 16 + g;
                af[i][0] = tf32r(As[(kb + tg) * ASTR + m]);
                af[i][1] = tf32r(As[(kb + tg) * ASTR + m + 8]);
                af[i][2] = tf32r(As[(kb + tg + 4) * ASTR + m]);
                af[i][3] = tf32r(As[(kb + tg + 4) * ASTR + m + 8]);
            }
            unsigned bf[4][2];
#pragma unroll
            for (int j = 0; j < 4; j++) {
                int n = nb + j * 8 + g;
                bf[j][0] = tf32r(Bs[n * BSTR + kb + tg]);
                bf[j][1] = tf32r(Bs[n * BSTR + kb + tg + 4]);
            }
#pragma unroll
            for (int i = 0; i < 4; i++)
#pragma unroll
                for (int j = 0; j < 4; j++)
                    mma_tf32(c[i][j], af[i], bf[j]);
        }
    }

    // epilogue: BN + ReLU, store float2 pairs (32B-sector complete per (row,j))
    const int mb = m0 + warp_m * 64;
    const int nbl = warp_n * 32;
#pragma unroll
    for (int i = 0; i < 4; i++) {
        int r0 = mb + i * 16 + g;
        float* op0 = g_feat + ((size_t)b * NPIX + r0) * CCH + n0;
        float* op1 = op0 + (size_t)8 * CCH;
#pragma unroll
        for (int j = 0; j < 4; j++) {
            int nl = nbl + j * 8 + 2 * tg;
            float s0 = bnS[nl], s1 = bnS[nl + 1];
            float u0 = bnM[nl], u1 = bnM[nl + 1];
            float t0 = bnT[nl], t1 = bnT[nl + 1];
            float2 v0, v1;
            v0.x = fmaxf((c[i][j][0] - u0) * s0 + t0, 0.f);
            v0.y = fmaxf((c[i][j][1] - u1) * s1 + t1, 0.f);
            v1.x = fmaxf((c[i][j][2] - u0) * s0 + t0, 0.f);
            v1.y = fmaxf((c[i][j][3] - u1) * s1 + t1, 0.f);
            *(float2*)(op0 + nl) = v0;
            *(float2*)(op1 + nl) = v1;
        }
    }
}

// ---------------- K2: scaled-L2 softmax assignment + aggregation ------------
#define CWS 520
__global__ __launch_bounds__(256, 2) void k_assign(
    const float* __restrict__ cw, const float* __restrict__ scale)
{
    extern __shared__ float sm[];
    float* cw_s = sm;                      // 32*520
    float* fr   = cw_s + KCODES * CWS;     // 512
    float* xc_s = fr + 512;                // 32
    float* aw_s = xc_s + 32;               // 32
    float* aws  = aw_s + 32;               // 32
    float* c2_s = aws + 32;                // 32
    float* sc_s = c2_s + 32;               // 32
    float* x2p  = sc_s + 32;               // 1

    const int tid = threadIdx.x;
    const int b   = blockIdx.x >> 6;
    const int n0  = (blockIdx.x & 63) * 256;

    for (int i = tid; i < KCODES * CCH; i += 256) {
        int k = i >> 9, c = i & 511;
        cw_s[k * CWS + c] = cw[i];
    }
    if (tid < 32) { sc_s[tid] = scale[tid]; aws[tid] = 0.f; }
    __syncthreads();

    const int kq = tid >> 3;
    const int cs = tid & 7;
    {
        float c2p = 0.f;
#pragma unroll 16
        for (int j = 0; j < 64; j++) {
            float v = cw_s[kq * CWS + cs + 8 * j];
            c2p += v * v;
        }
        c2p += __shfl_xor_sync(~0u, c2p, 4);
        c2p += __shfl_xor_sync(~0u, c2p, 2);
        c2p += __shfl_xor_sync(~0u, c2p, 1);
        if (cs == 0) c2_s[kq] = c2p;
    }

    float acc0[KCODES], acc1[KCODES];
#pragma unroll
    for (int k = 0; k < KCODES; k++) { acc0[k] = 0.f; acc1[k] = 0.f; }

    const float* fb = g_feat + ((size_t)b * NPIX + n0) * CCH;

    for (int p = 0; p < 256; p++) {
        __syncthreads();
        fr[tid]       = fb[(size_t)p * CCH + tid];
        fr[tid + 256] = fb[(size_t)p * CCH + tid + 256];
        __syncthreads();

        float dp = 0.f, p2 = 0.f;
#pragma unroll 16
        for (int j = 0; j < 64; j++) {
            float f = fr[cs + 8 * j];
            dp += f * cw_s[kq * CWS + cs + 8 * j];
            p2 += f * f;
        }
        dp += __shfl_xor_sync(~0u, dp, 4);
        dp += __shfl_xor_sync(~0u, dp, 2);
        dp += __shfl_xor_sync(~0u, dp, 1);
        p2 += __shfl_xor_sync(~0u, p2, 4);
        p2 += __shfl_xor_sync(~0u, p2, 2);
        p2 += __shfl_xor_sync(~0u, p2, 1);
        if (cs == 0) xc_s[kq] = dp;
        if (tid == 0) x2p[0] = p2;
        __syncthreads();

        if (tid < 32) {
            float l = sc_s[tid] * (x2p[0] - 2.f * xc_s[tid] + c2_s[tid]);
            float mx = l;
            mx = fmaxf(mx, __shfl_xor_sync(~0u, mx, 16));
            mx = fmaxf(mx, __shfl_xor_sync(~0u, mx, 8));
            mx = fmaxf(mx, __shfl_xor_sync(~0u, mx, 4));
            mx = fmaxf(mx, __shfl_xor_sync(~0u, mx, 2));
            mx = fmaxf(mx, __shfl_xor_sync(~0u, mx, 1));
            float e = __expf(l - mx);
            float s = e;
            s += __shfl_xor_sync(~0u, s, 16);
            s += __shfl_xor_sync(~0u, s, 8);
            s += __shfl_xor_sync(~0u, s, 4);
            s += __shfl_xor_sync(~0u, s, 2);
            s += __shfl_xor_sync(~0u, s, 1);
            float a = e / s;
            aw_s[tid] = a;
            aws[tid] += a;
        }
        __syncthreads();

        float f0 = fr[tid], f1 = fr[tid + 256];
#pragma unroll
        for (int k = 0; k < KCODES; k++) {
            float a = aw_s[k];
            acc0[k] += a * f0;
            acc1[k] += a * f1;
        }
    }

    float* eb = g_enc + (size_t)b * KCODES * CCH;
#pragma unroll
    for (int k = 0; k < KCODES; k++) {
        atomicAdd(&eb[k * CCH + tid], acc0[k]);
        atomicAdd(&eb[k * CCH + tid + 256], acc1[k]);
    }
    __syncthreads();
    if (tid < 32) atomicAdd(&g_awsum[b * KCODES + tid], aws[tid]);
}

// ---------------- K3: finalize enc -> BN1 + ReLU + mean over codes ----------
__global__ void k_final(const float* __restrict__ cw,
                        const float* __restrict__ g1, const float* __restrict__ b1,
                        const float* __restrict__ m1, const float* __restrict__ v1,
                        float* __restrict__ out)
{
    int b = blockIdx.x;
    int c = threadIdx.x;
    float sum = 0.f;
#pragma unroll
    for (int k = 0; k < KCODES; k++) {
        float e = g_enc[(b * KCODES + k) * CCH + c] - g_awsum[b * KCODES + k] * cw[k * CCH + c];
        float s = g1[k] * rsqrtf(v1[k] + EPS);
        e = (e - m1[k]) * s + b1[k];
        sum += fmaxf(e, 0.f);
    }
    float ef = sum * (1.f / (float)KCODES);
    g_encfeat[b * CCH + c] = ef;
    out[b * CCH + c] = ef;
}

// ---------------- K4: fc + sigmoid -> 1+gamma --------------------------------
__global__ void k_fc(const float* __restrict__ fcw, const float* __restrict__ fcb)
{
    int w = blockIdx.x * 8 + (threadIdx.x >> 5);
    int lane = threadIdx.x & 31;
    int b = w >> 9, co = w & 511;
    const float* wr = fcw + (size_t)co * CCH;
    const float* ef = g_encfeat + b * CCH;
    float s = 0.f;
#pragma unroll
    for (int j = 0; j < 16; j++) s += wr[lane + 32 * j] * ef[lane + 32 * j];
    s += __shfl_xor_sync(~0u, s, 16);
    s += __shfl_xor_sync(~0u, s, 8);
    s += __shfl_xor_sync(~0u, s, 4);
    s += __shfl_xor_sync(~0u, s, 2);
    s += __shfl_xor_sync(~0u, s, 1);
    if (lane == 0)
        g_gamma1p[w] = 1.f + 1.f / (1.f + __expf(-(s + fcb[co])));
}

// ---------------- K5: output = relu(x * (1+gamma)) ---------------------------
__global__ void k_out(const float4* __restrict__ x4, float4* __restrict__ o4, int n4)
{
    int i = blockIdx.x * blockDim.x + threadIdx.x;
    if (i >= n4) return;
    float g = g_gamma1p[i >> 12];
    float4 v = x4[i];
    v.x = fmaxf(v.x * g, 0.f);
    v.y = fmaxf(v.y * g, 0.f);
    v.z = fmaxf(v.z * g, 0.f);
    v.w = fmaxf(v.w * g, 0.f);
    o4[i] = v;
}

// ---------------- launch -----------------------------------------------------
extern "C" void kernel_launch(void* const* d_in, const int* in_sizes, int n_in,
                              void* d_out, int out_size)
{
    const float* x    = (const float*)d_in[0];
    const float* cwn  = (const float*)d_in[1];
    const float* b2g  = (const float*)d_in[2];
    const float* b2b  = (const float*)d_in[3];
    const float* b2m  = (const float*)d_in[4];
    const float* b2v  = (const float*)d_in[5];
    const float* cw   = (const float*)d_in[6];
    const float* sc   = (const float*)d_in[7];
    const float* b1g  = (const float*)d_in[8];
    const float* b1b  = (const float*)d_in[9];
    const float* b1m  = (const float*)d_in[10];
    const float* b1v  = (const float*)d_in[11];
    const float* fcw  = (const float*)d_in[12];
    const float* fcb  = (const float*)d_in[13];
    float* out = (float*)d_out;

    const int conv_smem = (2 * ATILE + 2 * BTILE) * 4;   // 75776 B
    cudaFuncSetAttribute(k_conv_mma, cudaFuncAttributeMaxDynamicSharedMemorySize,
                         conv_smem);
    const int assign_smem = (KCODES * CWS + 512 + 32 * 5 + 8) * 4;
    cudaFuncSetAttribute(k_assign, cudaFuncAttributeMaxDynamicSharedMemorySize,
                         assign_smem);

    k_zero<<<(BX * KCODES * CCH + 255) / 256, 256>>>();

    dim3 g1(NPIX / 128, CCH / 128, BX);
    k_conv_mma<<<g1, 256, conv_smem>>>(x, cwn, b2g, b2b, b2m, b2v);

    k_assign<<<BX * (NPIX / 256), 256, assign_smem>>>(cw, sc);

    k_final<<<BX, CCH>>>(cw, b1g, b1b, b1m, b1v, out);

    k_fc<<<BX * CCH / 8, 256>>>(fcw, fcb);

    int n4 = BX * CCH * NPIX / 4;
    k_out<<<n4 / 256, 256>>>((const float4*)x, (float4*)(out + BX * CCH), n4);
}

// round 5
// speedup vs baseline: 1.5899x; 1.1951x over previous
#include <cuda_runtime.h>
#include <cstdint>

#define EPS 1e-5f

#define BX 8
#define CCH 512
#define KCODES 32
#define NPIX 16384   // 128*128

// ---------------- device scratch ----------------
__device__ float g_feat[(size_t)BX * NPIX * CCH];   // [B][N][C]  268MB
__device__ float g_xr[(size_t)BX * CCH * NPIX];     // tf32-rounded x  268MB
__device__ float g_wr[CCH * CCH];                   // tf32-rounded w
__device__ float g_x2[BX * NPIX];                   // per-pixel |feat|^2
__device__ float g_enc[BX * KCODES * CCH];          // [B][K][C]
__device__ float g_awsum[BX * KCODES];              // [B][K]
__device__ float g_encfeat[BX * CCH];               // [B][C]
__device__ float g_gamma1p[BX * CCH];               // 1 + sigmoid(...)

// ---------------- helpers ----------------
__device__ __forceinline__ uint32_t smem_u32(const void* p) {
    uint32_t a;
    asm("{ .reg .u64 t; cvta.to.shared.u64 t, %1; cvt.u32.u64 %0, t; }" : "=r"(a) : "l"(p));
    return a;
}
__device__ __forceinline__ unsigned tf32r(float v) {
    unsigned u; asm("cvt.rna.tf32.f32 %0, %1;" : "=r"(u) : "f"(v)); return u;
}
#define CP16(dst, src) \
    asm volatile("cp.async.cg.shared.global [%0], [%1], 16;" :: "r"(dst), "l"(src))
#define CPCOMMIT() asm volatile("cp.async.commit_group;" ::: "memory")
#define CPWAIT0()  asm volatile("cp.async.wait_group 0;" ::: "memory")

__device__ __forceinline__ void mma_tf32(float* c, const unsigned* a, const unsigned* b) {
    asm volatile("mma.sync.aligned.m16n8k8.row.col.f32.tf32.tf32.f32 "
        "{%0,%1,%2,%3}, {%4,%5,%6,%7}, {%8,%9}, {%0,%1,%2,%3};"
        : "+f"(c[0]), "+f"(c[1]), "+f"(c[2]), "+f"(c[3])
        : "r"(a[0]), "r"(a[1]), "r"(a[2]), "r"(a[3]), "r"(b[0]), "r"(b[1]));
}

// ---------------- K0: zero accumulators ----------------
__global__ void k_zero() {
    int i = blockIdx.x * 256 + threadIdx.x;
    if (i < BX * KCODES * CCH) g_enc[i] = 0.f;     // 131072
    if (i < BX * NPIX) g_x2[i] = 0.f;              // 131072
    if (i < BX * KCODES) g_awsum[i] = 0.f;
}

// ---------------- Kpre: tf32-round x and w into scratch ----------------
#define NX4 ((size_t)BX * CCH * NPIX / 4)   // 16777216
#define NW4 (CCH * CCH / 4)                 // 65536
__global__ void k_pre(const float4* __restrict__ x, const float4* __restrict__ w)
{
    size_t i = (size_t)blockIdx.x * 256 + threadIdx.x;
    if (i < NX4) {
        float4 v = x[i];
        float4 o;
        o.x = __uint_as_float(tf32r(v.x));
        o.y = __uint_as_float(tf32r(v.y));
        o.z = __uint_as_float(tf32r(v.z));
        o.w = __uint_as_float(tf32r(v.w));
        ((float4*)g_xr)[i] = o;
    } else if (i - NX4 < NW4) {
        size_t j = i - NX4;
        float4 v = w[j];
        float4 o;
        o.x = __uint_as_float(tf32r(v.x));
        o.y = __uint_as_float(tf32r(v.y));
        o.z = __uint_as_float(tf32r(v.z));
        o.w = __uint_as_float(tf32r(v.w));
        ((float4*)g_wr)[j] = o;
    }
}

// ---------------- K1: conv(1x1)+BN2+ReLU via mma.sync tf32 (no cvt in loop) --
#define ASTR 136
#define BSTR 40
#define ATILE (32 * ASTR)   // 4352 floats
#define BTILE (128 * BSTR)  // 5120 floats

__global__ __launch_bounds__(256, 2) void k_conv_mma(
    const float* __restrict__ bg, const float* __restrict__ bb,
    const float* __restrict__ bm, const float* __restrict__ bv)
{
    extern __shared__ float dsm[];
    float* Abuf[2] = { dsm, dsm + ATILE };
    float* Bbuf[2] = { dsm + 2 * ATILE, dsm + 2 * ATILE + BTILE };
    __shared__ float bnS[128], bnM[128], bnT[128];

    const int tid  = threadIdx.x;
    const int wid  = tid >> 5;
    const int lane = tid & 31;
    const int g    = lane >> 2;
    const int tg   = lane & 3;
    const int warp_m = wid >> 2;    // 0..1
    const int warp_n = wid & 3;     // 0..3

    const int b  = blockIdx.z;
    const int m0 = blockIdx.x * 128;
    const int n0 = blockIdx.y * 128;

    if (tid < 128) {
        int n = n0 + tid;
        bnS[tid] = bg[n] * rsqrtf(bv[n] + EPS);
        bnM[tid] = bm[n];
        bnT[tid] = bb[n];
    }

    const float* xb = g_xr + (size_t)b * CCH * NPIX;

    const int arow = tid >> 3;            // k-row 0..31
    const int mseg = (tid & 7) * 16;      // m 0..112
    const int bn   = tid >> 1;            // n 0..127
    const int koff = (tid & 1) * 16;      // k sub 0/16

    {
        const float* asrc = xb + (size_t)arow * NPIX + m0 + mseg;
        uint32_t adst = smem_u32(Abuf[0] + arow * ASTR + mseg);
#pragma unroll
        for (int j = 0; j < 4; j++) CP16(adst + j * 16, asrc + j * 4);
        const float* bsrc = g_wr + (size_t)(n0 + bn) * CCH + koff;
        uint32_t bdst = smem_u32(Bbuf[0] + bn * BSTR + koff);
#pragma unroll
        for (int j = 0; j < 4; j++) CP16(bdst + j * 16, bsrc + j * 4);
        CPCOMMIT();
    }

    float c[4][4][4];
#pragma unroll
    for (int i = 0; i < 4; i++)
#pragma unroll
        for (int j = 0; j < 4; j++)
#pragma unroll
            for (int r = 0; r < 4; r++) c[i][j][r] = 0.f;

    for (int kt = 0; kt < 16; kt++) {
        CPWAIT0();
        __syncthreads();

        if (kt < 15) {
            int k0 = (kt + 1) * 32;
            const float* asrc = xb + (size_t)(k0 + arow) * NPIX + m0 + mseg;
            uint32_t adst = smem_u32(Abuf[(kt + 1) & 1] + arow * ASTR + mseg);
#pragma unroll
            for (int j = 0; j < 4; j++) CP16(adst + j * 16, asrc + j * 4);
            const float* bsrc = g_wr + (size_t)(n0 + bn) * CCH + k0 + koff;
            uint32_t bdst = smem_u32(Bbuf[(kt + 1) & 1] + bn * BSTR + koff);
#pragma unroll
            for (int j = 0; j < 4; j++) CP16(bdst + j * 16, bsrc + j * 4);
            CPCOMMIT();
        }

        const unsigned* As = (const unsigned*)Abuf[kt & 1];
        const unsigned* Bs = (const unsigned*)Bbuf[kt & 1];
        const int mb = warp_m * 64;
        const int nb = warp_n * 32;

#pragma unroll
        for (int s = 0; s < 4; s++) {
            const int kb = s * 8;
            unsigned af[4][4];
#pragma unroll
            for (int i = 0; i < 4; i++) {
                int m = mb + i * 16 + g;
                af[i][0] = As[(kb + tg) * ASTR + m];
                af[i][1] = As[(kb + tg) * ASTR + m + 8];
                af[i][2] = As[(kb + tg + 4) * ASTR + m];
                af[i][3] = As[(kb + tg + 4) * ASTR + m + 8];
            }
            unsigned bf[4][2];
#pragma unroll
            for (int j = 0; j < 4; j++) {
                int n = nb + j * 8 + g;
                bf[j][0] = Bs[n * BSTR + kb + tg];
                bf[j][1] = Bs[n * BSTR + kb + tg + 4];
            }
#pragma unroll
            for (int i = 0; i < 4; i++)
#pragma unroll
                for (int j = 0; j < 4; j++)
                    mma_tf32(c[i][j], af[i], bf[j]);
        }
    }

    // epilogue: BN + ReLU + store + per-pixel sum-of-squares partial -> g_x2
    const int mb = m0 + warp_m * 64;
    const int nbl = warp_n * 32;
#pragma unroll
    for (int i = 0; i < 4; i++) {
        int r0 = mb + i * 16 + g;
        float* op0 = g_feat + ((size_t)b * NPIX + r0) * CCH + n0;
        float* op1 = op0 + (size_t)8 * CCH;
        float s0 = 0.f, s1 = 0.f;
#pragma unroll
        for (int j = 0; j < 4; j++) {
            int nl = nbl + j * 8 + 2 * tg;
            float sc0 = bnS[nl], sc1 = bnS[nl + 1];
            float u0 = bnM[nl], u1 = bnM[nl + 1];
            float t0 = bnT[nl], t1 = bnT[nl + 1];
            float2 v0, v1;
            v0.x = fmaxf((c[i][j][0] - u0) * sc0 + t0, 0.f);
            v0.y = fmaxf((c[i][j][1] - u1) * sc1 + t1, 0.f);
            v1.x = fmaxf((c[i][j][2] - u0) * sc0 + t0, 0.f);
            v1.y = fmaxf((c[i][j][3] - u1) * sc1 + t1, 0.f);
            *(float2*)(op0 + nl) = v0;
            *(float2*)(op1 + nl) = v1;
            s0 += v0.x * v0.x + v0.y * v0.y;
            s1 += v1.x * v1.x + v1.y * v1.y;
        }
        s0 += __shfl_xor_sync(~0u, s0, 1);
        s0 += __shfl_xor_sync(~0u, s0, 2);
        s1 += __shfl_xor_sync(~0u, s1, 1);
        s1 += __shfl_xor_sync(~0u, s1, 2);
        if (tg == 0) {
            atomicAdd(&g_x2[b * NPIX + r0], s0);
            atomicAdd(&g_x2[b * NPIX + r0 + 8], s1);
        }
    }
}

// ---------------- K2: scaled-L2 softmax assignment + aggregation ------------
// 2 pixels per iteration; x2 precomputed; cw smem reads shared by both pixels.
#define CWS 520
__global__ __launch_bounds__(256, 2) void k_assign(
    const float* __restrict__ cw, const float* __restrict__ scale)
{
    extern __shared__ float sm[];
    float* cw_s = sm;                      // 32*520
    float* fr   = cw_s + KCODES * CWS;     // 1024  (2 pixel rows)
    float* x2_s = fr + 1024;               // 256
    float* xc_s = x2_s + 256;              // 64
    float* aw_s = xc_s + 64;               // 64
    float* awsA = aw_s + 64;               // 64
    float* c2_s = awsA + 64;               // 32
    float* sc_s = c2_s + 32;               // 32

    const int tid = threadIdx.x;
    const int b   = blockIdx.x >> 6;
    const int n0  = (blockIdx.x & 63) * 256;

    for (int i = tid; i < KCODES * CCH; i += 256) {
        int k = i >> 9, c = i & 511;
        cw_s[k * CWS + c] = cw[i];
    }
    if (tid < 32) sc_s[tid] = scale[tid];
    if (tid < 64) awsA[tid] = 0.f;
    x2_s[tid] = g_x2[b * NPIX + n0 + tid];
    __syncthreads();

    const int kq = tid >> 3;
    const int cs = tid & 7;
    {
        float c2p = 0.f;
#pragma unroll 16
        for (int j = 0; j < 64; j++) {
            float v = cw_s[kq * CWS + cs + 8 * j];
            c2p += v * v;
        }
        c2p += __shfl_xor_sync(~0u, c2p, 4);
        c2p += __shfl_xor_sync(~0u, c2p, 2);
        c2p += __shfl_xor_sync(~0u, c2p, 1);
        if (cs == 0) c2_s[kq] = c2p;
    }

    float acc0[KCODES], acc1[KCODES];
#pragma unroll
    for (int k = 0; k < KCODES; k++) { acc0[k] = 0.f; acc1[k] = 0.f; }

    const float* fb = g_feat + ((size_t)b * NPIX + n0) * CCH;

    for (int pp = 0; pp < 128; pp++) {
        __syncthreads();
        const float* fa = fb + (size_t)(2 * pp) * CCH;
        fr[tid]        = fa[tid];
        fr[tid + 256]  = fa[tid + 256];
        fr[tid + 512]  = fa[tid + CCH];
        fr[tid + 768]  = fa[tid + CCH + 256];
        __syncthreads();

        float dpa = 0.f, dpb = 0.f;
#pragma unroll 16
        for (int j = 0; j < 64; j++) {
            float cv = cw_s[kq * CWS + cs + 8 * j];
            dpa += fr[cs + 8 * j] * cv;
            dpb += fr[512 + cs + 8 * j] * cv;
        }
        dpa += __shfl_xor_sync(~0u, dpa, 4);
        dpa += __shfl_xor_sync(~0u, dpa, 2);
        dpa += __shfl_xor_sync(~0u, dpa, 1);
        dpb += __shfl_xor_sync(~0u, dpb, 4);
        dpb += __shfl_xor_sync(~0u, dpb, 2);
        dpb += __shfl_xor_sync(~0u, dpb, 1);
        if (cs == 0) { xc_s[kq] = dpa; xc_s[32 + kq] = dpb; }
        __syncthreads();

        if (tid < 64) {
            int wv = tid >> 5;   // pixel within pair
            int k  = tid & 31;
            float l = sc_s[k] * (x2_s[2 * pp + wv] - 2.f * xc_s[wv * 32 + k] + c2_s[k]);
            float mx = l;
            mx = fmaxf(mx, __shfl_xor_sync(~0u, mx, 16));
            mx = fmaxf(mx, __shfl_xor_sync(~0u, mx, 8));
            mx = fmaxf(mx, __shfl_xor_sync(~0u, mx, 4));
            mx = fmaxf(mx, __shfl_xor_sync(~0u, mx, 2));
            mx = fmaxf(mx, __shfl_xor_sync(~0u, mx, 1));
            float e = __expf(l - mx);
            float s = e;
            s += __shfl_xor_sync(~0u, s, 16);
            s += __shfl_xor_sync(~0u, s, 8);
            s += __shfl_xor_sync(~0u, s, 4);
            s += __shfl_xor_sync(~0u, s, 2);
            s += __shfl_xor_sync(~0u, s, 1);
            float a = e / s;
            aw_s[tid] = a;
            awsA[tid] += a;
        }
        __syncthreads();

        float fa0 = fr[tid], fa1 = fr[tid + 256];
        float fb0 = fr[tid + 512], fb1 = fr[tid + 768];
#pragma unroll
        for (int k = 0; k < KCODES; k++) {
            float a0 = aw_s[k];
            float a1 = aw_s[32 + k];
            acc0[k] += a0 * fa0 + a1 * fb0;
            acc1[k] += a0 * fa1 + a1 * fb1;
        }
    }

    float* eb = g_enc + (size_t)b * KCODES * CCH;
#pragma unroll
    for (int k = 0; k < KCODES; k++) {
        atomicAdd(&eb[k * CCH + tid], acc0[k]);
        atomicAdd(&eb[k * CCH + tid + 256], acc1[k]);
    }
    __syncthreads();
    if (tid < 32) atomicAdd(&g_awsum[b * KCODES + tid], awsA[tid] + awsA[32 + tid]);
}

// ---------------- K3: finalize enc -> BN1 + ReLU + mean over codes ----------
__global__ void k_final(const float* __restrict__ cw,
                        const float* __restrict__ g1, const float* __restrict__ b1,
                        const float* __restrict__ m1, const float* __restrict__ v1,
                        float* __restrict__ out)
{
    int b = blockIdx.x;
    int c = threadIdx.x;
    float sum = 0.f;
#pragma unroll
    for (int k = 0; k < KCODES; k++) {
        float e = g_enc[(b * KCODES + k) * CCH + c] - g_awsum[b * KCODES + k] * cw[k * CCH + c];
        float s = g1[k] * rsqrtf(v1[k] + EPS);
        e = (e - m1[k]) * s + b1[k];
        sum += fmaxf(e, 0.f);
    }
    float ef = sum * (1.f / (float)KCODES);
    g_encfeat[b * CCH + c] = ef;
    out[b * CCH + c] = ef;
}

// ---------------- K4: fc + sigmoid -> 1+gamma --------------------------------
__global__ void k_fc(const float* __restrict__ fcw, const float* __restrict__ fcb)
{
    int w = blockIdx.x * 8 + (threadIdx.x >> 5);
    int lane = threadIdx.x & 31;
    int b = w >> 9, co = w & 511;
    const float* wr = fcw + (size_t)co * CCH;
    const float* ef = g_encfeat + b * CCH;
    float s = 0.f;
#pragma unroll
    for (int j = 0; j < 16; j++) s += wr[lane + 32 * j] * ef[lane + 32 * j];
    s += __shfl_xor_sync(~0u, s, 16);
    s += __shfl_xor_sync(~0u, s, 8);
    s += __shfl_xor_sync(~0u, s, 4);
    s += __shfl_xor_sync(~0u, s, 2);
    s += __shfl_xor_sync(~0u, s, 1);
    if (lane == 0)
        g_gamma1p[w] = 1.f + 1.f / (1.f + __expf(-(s + fcb[co])));
}

// ---------------- K5: output = relu(x * (1+gamma)) ---------------------------
__global__ void k_out(const float4* __restrict__ x4, float4* __restrict__ o4, int n4)
{
    int i = blockIdx.x * blockDim.x + threadIdx.x;
    if (i >= n4) return;
    float g = g_gamma1p[i >> 12];
    float4 v = x4[i];
    v.x = fmaxf(v.x * g, 0.f);
    v.y = fmaxf(v.y * g, 0.f);
    v.z = fmaxf(v.z * g, 0.f);
    v.w = fmaxf(v.w * g, 0.f);
    o4[i] = v;
}

// ---------------- launch -----------------------------------------------------
extern "C" void kernel_launch(void* const* d_in, const int* in_sizes, int n_in,
                              void* d_out, int out_size)
{
    const float* x    = (const float*)d_in[0];
    const float* cwn  = (const float*)d_in[1];
    const float* b2g  = (const float*)d_in[2];
    const float* b2b  = (const float*)d_in[3];
    const float* b2m  = (const float*)d_in[4];
    const float* b2v  = (const float*)d_in[5];
    const float* cw   = (const float*)d_in[6];
    const float* sc   = (const float*)d_in[7];
    const float* b1g  = (const float*)d_in[8];
    const float* b1b  = (const float*)d_in[9];
    const float* b1m  = (const float*)d_in[10];
    const float* b1v  = (const float*)d_in[11];
    const float* fcw  = (const float*)d_in[12];
    const float* fcb  = (const float*)d_in[13];
    float* out = (float*)d_out;

    const int conv_smem = (2 * ATILE + 2 * BTILE) * 4;   // 75776 B
    cudaFuncSetAttribute(k_conv_mma, cudaFuncAttributeMaxDynamicSharedMemorySize,
                         conv_smem);
    const int assign_smem = (KCODES * CWS + 1024 + 256 + 64 * 3 + 64 + 8) * 4;
    cudaFuncSetAttribute(k_assign, cudaFuncAttributeMaxDynamicSharedMemorySize,
                         assign_smem);

    k_zero<<<(BX * KCODES * CCH + 255) / 256, 256>>>();

    k_pre<<<(int)((NX4 + NW4 + 255) / 256), 256>>>((const float4*)x, (const float4*)cwn);

    dim3 g1(NPIX / 128, CCH / 128, BX);
    k_conv_mma<<<g1, 256, conv_smem>>>(b2g, b2b, b2m, b2v);

    k_assign<<<BX * (NPIX / 256), 256, assign_smem>>>(cw, sc);

    k_final<<<BX, CCH>>>(cw, b1g, b1b, b1m, b1v, out);

    k_fc<<<BX * CCH / 8, 256>>>(fcw, fcb);

    int n4 = BX * CCH * NPIX / 4;
    k_out<<<n4 / 256, 256>>>((const float4*)x, (float4*)(out + BX * CCH), n4);
}

// round 6
// speedup vs baseline: 1.7199x; 1.0818x over previous
#include <cuda_runtime.h>
#include <cstdint>

#define EPS 1e-5f

#define BX 8
#define CCH 512
#define KCODES 32
#define NPIX 16384   // 128*128

// ---------------- device scratch ----------------
__device__ float g_feat[(size_t)BX * NPIX * CCH];   // [B][N][C] tf32-rounded, 268MB
__device__ float g_xr[(size_t)BX * CCH * NPIX];     // tf32-rounded x  268MB
__device__ float g_wr[CCH * CCH];                   // tf32-rounded w
__device__ float g_cwr[KCODES * CCH];               // tf32-rounded codewords
__device__ float g_aw[(size_t)BX * NPIX * KCODES];  // softmax weights (tf32-rounded), 67MB
__device__ float g_x2[BX * NPIX];                   // per-pixel |feat|^2
__device__ float g_c2[KCODES];                      // |cw|^2
__device__ float g_enc[BX * KCODES * CCH];          // [B][K][C]
__device__ float g_awsum[BX * KCODES];              // [B][K]
__device__ float g_encfeat[BX * CCH];               // [B][C]
__device__ float g_gamma1p[BX * CCH];               // 1 + sigmoid(...)

// ---------------- helpers ----------------
__device__ __forceinline__ uint32_t smem_u32(const void* p) {
    uint32_t a;
    asm("{ .reg .u64 t; cvta.to.shared.u64 t, %1; cvt.u32.u64 %0, t; }" : "=r"(a) : "l"(p));
    return a;
}
__device__ __forceinline__ unsigned tf32r(float v) {
    unsigned u; asm("cvt.rna.tf32.f32 %0, %1;" : "=r"(u) : "f"(v)); return u;
}
__device__ __forceinline__ float tf32f(float v) { return __uint_as_float(tf32r(v)); }
#define CP16(dst, src) \
    asm volatile("cp.async.cg.shared.global [%0], [%1], 16;" :: "r"(dst), "l"(src))
#define CPCOMMIT() asm volatile("cp.async.commit_group;" ::: "memory")
#define CPWAIT0()  asm volatile("cp.async.wait_group 0;" ::: "memory")
#define CPWAIT1()  asm volatile("cp.async.wait_group 1;" ::: "memory")

__device__ __forceinline__ void mma_tf32(float* c, const unsigned* a, const unsigned* b) {
    asm volatile("mma.sync.aligned.m16n8k8.row.col.f32.tf32.tf32.f32 "
        "{%0,%1,%2,%3}, {%4,%5,%6,%7}, {%8,%9}, {%0,%1,%2,%3};"
        : "+f"(c[0]), "+f"(c[1]), "+f"(c[2]), "+f"(c[3])
        : "r"(a[0]), "r"(a[1]), "r"(a[2]), "r"(a[3]), "r"(b[0]), "r"(b[1]));
}

// ---------------- K0: zero accumulators ----------------
__global__ void k_zero() {
    int i = blockIdx.x * 256 + threadIdx.x;
    if (i < BX * KCODES * CCH) g_enc[i] = 0.f;
    if (i < BX * NPIX) g_x2[i] = 0.f;
    if (i < BX * KCODES) g_awsum[i] = 0.f;
}

// ---------------- Kpre: tf32-round x, w, cw into scratch ----------------
#define NX4 ((size_t)BX * CCH * NPIX / 4)   // 16777216
#define NW4 (CCH * CCH / 4)                 // 65536
#define NC4 (KCODES * CCH / 4)              // 4096
__global__ void k_pre(const float4* __restrict__ x, const float4* __restrict__ w,
                      const float4* __restrict__ cw)
{
    size_t i = (size_t)blockIdx.x * 256 + threadIdx.x;
    float4 v, o;
    if (i < NX4) {
        v = x[i];
        o.x = tf32f(v.x); o.y = tf32f(v.y); o.z = tf32f(v.z); o.w = tf32f(v.w);
        ((float4*)g_xr)[i] = o;
    } else if (i - NX4 < NW4) {
        size_t j = i - NX4;
        v = w[j];
        o.x = tf32f(v.x); o.y = tf32f(v.y); o.z = tf32f(v.z); o.w = tf32f(v.w);
        ((float4*)g_wr)[j] = o;
    } else if (i - NX4 - NW4 < NC4) {
        size_t j = i - NX4 - NW4;
        v = cw[j];
        o.x = tf32f(v.x); o.y = tf32f(v.y); o.z = tf32f(v.z); o.w = tf32f(v.w);
        ((float4*)g_cwr)[j] = o;
    }
}

// ---------------- Kc2: |cw|^2 per code ----------------
__global__ void k_c2(const float* __restrict__ cw) {
    int code = threadIdx.x >> 5;
    int lane = threadIdx.x & 31;
    float s = 0.f;
#pragma unroll
    for (int j = 0; j < 16; j++) {
        float v = cw[code * CCH + lane + 32 * j];
        s += v * v;
    }
    s += __shfl_xor_sync(~0u, s, 16);
    s += __shfl_xor_sync(~0u, s, 8);
    s += __shfl_xor_sync(~0u, s, 4);
    s += __shfl_xor_sync(~0u, s, 2);
    s += __shfl_xor_sync(~0u, s, 1);
    if (lane == 0) g_c2[code] = s;
}

// ---------------- K1: conv(1x1)+BN2+ReLU via mma.sync tf32 ----------------
#define ASTR 136
#define BSTR 40
#define ATILE (32 * ASTR)
#define BTILE (128 * BSTR)

__global__ __launch_bounds__(256, 2) void k_conv_mma(
    const float* __restrict__ bg, const float* __restrict__ bb,
    const float* __restrict__ bm, const float* __restrict__ bv)
{
    extern __shared__ float dsm[];
    float* Abuf[2] = { dsm, dsm + ATILE };
    float* Bbuf[2] = { dsm + 2 * ATILE, dsm + 2 * ATILE + BTILE };
    __shared__ float bnS[128], bnM[128], bnT[128];

    const int tid  = threadIdx.x;
    const int wid  = tid >> 5;
    const int lane = tid & 31;
    const int g    = lane >> 2;
    const int tg   = lane & 3;
    const int warp_m = wid >> 2;
    const int warp_n = wid & 3;

    const int b  = blockIdx.z;
    const int m0 = blockIdx.x * 128;
    const int n0 = blockIdx.y * 128;

    if (tid < 128) {
        int n = n0 + tid;
        bnS[tid] = bg[n] * rsqrtf(bv[n] + EPS);
        bnM[tid] = bm[n];
        bnT[tid] = bb[n];
    }

    const float* xb = g_xr + (size_t)b * CCH * NPIX;

    const int arow = tid >> 3;
    const int mseg = (tid & 7) * 16;
    const int bn   = tid >> 1;
    const int koff = (tid & 1) * 16;

    {
        const float* asrc = xb + (size_t)arow * NPIX + m0 + mseg;
        uint32_t adst = smem_u32(Abuf[0] + arow * ASTR + mseg);
#pragma unroll
        for (int j = 0; j < 4; j++) CP16(adst + j * 16, asrc + j * 4);
        const float* bsrc = g_wr + (size_t)(n0 + bn) * CCH + koff;
        uint32_t bdst = smem_u32(Bbuf[0] + bn * BSTR + koff);
#pragma unroll
        for (int j = 0; j < 4; j++) CP16(bdst + j * 16, bsrc + j * 4);
        CPCOMMIT();
    }

    float c[4][4][4];
#pragma unroll
    for (int i = 0; i < 4; i++)
#pragma unroll
        for (int j = 0; j < 4; j++)
#pragma unroll
            for (int r = 0; r < 4; r++) c[i][j][r] = 0.f;

    for (int kt = 0; kt < 16; kt++) {
        CPWAIT0();
        __syncthreads();

        if (kt < 15) {
            int k0 = (kt + 1) * 32;
            const float* asrc = xb + (size_t)(k0 + arow) * NPIX + m0 + mseg;
            uint32_t adst = smem_u32(Abuf[(kt + 1) & 1] + arow * ASTR + mseg);
#pragma unroll
            for (int j = 0; j < 4; j++) CP16(adst + j * 16, asrc + j * 4);
            const float* bsrc = g_wr + (size_t)(n0 + bn) * CCH + k0 + koff;
            uint32_t bdst = smem_u32(Bbuf[(kt + 1) & 1] + bn * BSTR + koff);
#pragma unroll
            for (int j = 0; j < 4; j++) CP16(bdst + j * 16, bsrc + j * 4);
            CPCOMMIT();
        }

        const unsigned* As = (const unsigned*)Abuf[kt & 1];
        const unsigned* Bs = (const unsigned*)Bbuf[kt & 1];
        const int mb = warp_m * 64;
        const int nb = warp_n * 32;

#pragma unroll
        for (int s = 0; s < 4; s++) {
            const int kb = s * 8;
            unsigned af[4][4];
#pragma unroll
            for (int i = 0; i < 4; i++) {
                int m = mb + i * 16 + g;
                af[i][0] = As[(kb + tg) * ASTR + m];
                af[i][1] = As[(kb + tg) * ASTR + m + 8];
                af[i][2] = As[(kb + tg + 4) * ASTR + m];
                af[i][3] = As[(kb + tg + 4) * ASTR + m + 8];
            }
            unsigned bf[4][2];
#pragma unroll
            for (int j = 0; j < 4; j++) {
                int n = nb + j * 8 + g;
                bf[j][0] = Bs[n * BSTR + kb + tg];
                bf[j][1] = Bs[n * BSTR + kb + tg + 4];
            }
#pragma unroll
            for (int i = 0; i < 4; i++)
#pragma unroll
                for (int j = 0; j < 4; j++)
                    mma_tf32(c[i][j], af[i], bf[j]);
        }
    }

    // epilogue: BN + ReLU + tf32-round + store + per-pixel |feat|^2 partial
    const int mb = m0 + warp_m * 64;
    const int nbl = warp_n * 32;
#pragma unroll
    for (int i = 0; i < 4; i++) {
        int r0 = mb + i * 16 + g;
        float* op0 = g_feat + ((size_t)b * NPIX + r0) * CCH + n0;
        float* op1 = op0 + (size_t)8 * CCH;
        float s0 = 0.f, s1 = 0.f;
#pragma unroll
        for (int j = 0; j < 4; j++) {
            int nl = nbl + j * 8 + 2 * tg;
            float sc0 = bnS[nl], sc1 = bnS[nl + 1];
            float u0 = bnM[nl], u1 = bnM[nl + 1];
            float t0 = bnT[nl], t1 = bnT[nl + 1];
            float2 v0, v1;
            v0.x = tf32f(fmaxf((c[i][j][0] - u0) * sc0 + t0, 0.f));
            v0.y = tf32f(fmaxf((c[i][j][1] - u1) * sc1 + t1, 0.f));
            v1.x = tf32f(fmaxf((c[i][j][2] - u0) * sc0 + t0, 0.f));
            v1.y = tf32f(fmaxf((c[i][j][3] - u1) * sc1 + t1, 0.f));
            *(float2*)(op0 + nl) = v0;
            *(float2*)(op1 + nl) = v1;
            s0 += v0.x * v0.x + v0.y * v0.y;
            s1 += v1.x * v1.x + v1.y * v1.y;
        }
        s0 += __shfl_xor_sync(~0u, s0, 1);
        s0 += __shfl_xor_sync(~0u, s0, 2);
        s1 += __shfl_xor_sync(~0u, s1, 1);
        s1 += __shfl_xor_sync(~0u, s1, 2);
        if (tg == 0) {
            atomicAdd(&g_x2[b * NPIX + r0], s0);
            atomicAdd(&g_x2[b * NPIX + r0 + 8], s1);
        }
    }
}

// ---------------- K2a: logits GEMM + softmax -> g_aw ----------------
// Block: 256 pixels, 8 warps (each 32 pixels), N=32 codes, K=512 (chunks of 32).
#define LSTR 36
#define CWSTR 516
#define AWSTR 33
__global__ __launch_bounds__(256) void k_logits(const float* __restrict__ scale)
{
    extern __shared__ float ls[];
    float* fbuf[2] = { ls, ls + 256 * LSTR };
    float* cw_s  = ls + 2 * 256 * LSTR;          // 32 x 516
    float* aw_s  = cw_s + 32 * CWSTR;            // 256 x 33
    float* sc_s  = aw_s + 256 * AWSTR;           // 32
    float* c2_s  = sc_s + 32;                    // 32
    float* x2_s  = c2_s + 32;                    // 256
    float* aws_s = x2_s + 256;                   // 32

    const int tid  = threadIdx.x;
    const int wid  = tid >> 5;
    const int lane = tid & 31;
    const int g    = lane >> 2;
    const int tg   = lane & 3;
    const int b  = blockIdx.x >> 6;
    const int n0 = (blockIdx.x & 63) * 256;

    // cw load (once) via cp.async
    {
        uint32_t cwb = smem_u32(cw_s);
#pragma unroll
        for (int jj = 0; jj < 16; jj++) {
            int idx = tid + 256 * jj;
            int row = idx >> 7, col = idx & 127;
            CP16(cwb + row * (CWSTR * 4) + col * 16, g_cwr + row * CCH + col * 4);
        }
    }
    if (tid < 32) { sc_s[tid] = scale[tid]; c2_s[tid] = g_c2[tid]; aws_s[tid] = 0.f; }
    x2_s[tid] = g_x2[b * NPIX + n0 + tid];

    const float* fb = g_feat + ((size_t)b * NPIX + n0) * CCH;
    const int frow = tid >> 3;        // 0..31
    const int fcol = tid & 7;         // 16B unit

    // prologue chunk 0
    {
        uint32_t d = smem_u32(fbuf[0]);
#pragma unroll
        for (int jj = 0; jj < 8; jj++) {
            int r = frow + 32 * jj;
            CP16(d + r * (LSTR * 4) + fcol * 16, fb + (size_t)r * CCH + fcol * 4);
        }
        CPCOMMIT();
    }

    float c[2][4][4];
#pragma unroll
    for (int i = 0; i < 2; i++)
#pragma unroll
        for (int j = 0; j < 4; j++)
#pragma unroll
            for (int r = 0; r < 4; r++) c[i][j][r] = 0.f;

    const int pb = wid * 32;

    for (int ch = 0; ch < 16; ch++) {
        if (ch < 15) {
            uint32_t d = smem_u32(fbuf[(ch + 1) & 1]);
            const float* src = fb + (ch + 1) * 32 + fcol * 4;
#pragma unroll
            for (int jj = 0; jj < 8; jj++) {
                int r = frow + 32 * jj;
                CP16(d + r * (LSTR * 4) + fcol * 16, src + (size_t)r * CCH);
            }
            CPCOMMIT();
            CPWAIT1();
        } else {
            CPWAIT0();
        }
        __syncthreads();

        const unsigned* F = (const unsigned*)fbuf[ch & 1];
        const unsigned* W = (const unsigned*)cw_s;
        const int kc = ch * 32;
#pragma unroll
        for (int k8 = 0; k8 < 4; k8++) {
            const int kb = k8 * 8;
            unsigned af[2][4];
#pragma unroll
            for (int i = 0; i < 2; i++) {
                int m = pb + i * 16 + g;
                af[i][0] = F[m * LSTR + kb + tg];
                af[i][1] = F[(m + 8) * LSTR + kb + tg];
                af[i][2] = F[m * LSTR + kb + tg + 4];
                af[i][3] = F[(m + 8) * LSTR + kb + tg + 4];
            }
            unsigned bf[4][2];
#pragma unroll
            for (int j = 0; j < 4; j++) {
                int n = j * 8 + g;
                bf[j][0] = W[n * CWSTR + kc + kb + tg];
                bf[j][1] = W[n * CWSTR + kc + kb + tg + 4];
            }
#pragma unroll
            for (int i = 0; i < 2; i++)
#pragma unroll
                for (int j = 0; j < 4; j++)
                    mma_tf32(c[i][j], af[i], bf[j]);
        }
        __syncthreads();
    }

    // softmax per pixel row (32 codes spread over quad: 8 values/thread)
#pragma unroll
    for (int i = 0; i < 2; i++) {
        int r0 = pb + i * 16 + g;
        int r1 = r0 + 8;
        float l0[8], l1[8];
#pragma unroll
        for (int j = 0; j < 4; j++)
#pragma unroll
            for (int h = 0; h < 2; h++) {
                int n = j * 8 + 2 * tg + h;
                l0[j * 2 + h] = sc_s[n] * (x2_s[r0] - 2.f * c[i][j][h] + c2_s[n]);
                l1[j * 2 + h] = sc_s[n] * (x2_s[r1] - 2.f * c[i][j][2 + h] + c2_s[n]);
            }
        float m0 = l0[0], m1 = l1[0];
#pragma unroll
        for (int q = 1; q < 8; q++) { m0 = fmaxf(m0, l0[q]); m1 = fmaxf(m1, l1[q]); }
        m0 = fmaxf(m0, __shfl_xor_sync(~0u, m0, 1));
        m0 = fmaxf(m0, __shfl_xor_sync(~0u, m0, 2));
        m1 = fmaxf(m1, __shfl_xor_sync(~0u, m1, 1));
        m1 = fmaxf(m1, __shfl_xor_sync(~0u, m1, 2));
        float s0 = 0.f, s1 = 0.f;
#pragma unroll
        for (int q = 0; q < 8; q++) {
            l0[q] = __expf(l0[q] - m0); s0 += l0[q];
            l1[q] = __expf(l1[q] - m1); s1 += l1[q];
        }
        s0 += __shfl_xor_sync(~0u, s0, 1);
        s0 += __shfl_xor_sync(~0u, s0, 2);
        s1 += __shfl_xor_sync(~0u, s1, 1);
        s1 += __shfl_xor_sync(~0u, s1, 2);
        float r0i = 1.f / s0, r1i = 1.f / s1;
#pragma unroll
        for (int j = 0; j < 4; j++)
#pragma unroll
            for (int h = 0; h < 2; h++) {
                int n = j * 8 + 2 * tg + h;
                aw_s[r0 * AWSTR + n] = tf32f(l0[j * 2 + h] * r0i);
                aw_s[r1 * AWSTR + n] = tf32f(l1[j * 2 + h] * r1i);
            }
    }
    __syncthreads();

    // coalesced store + awsum
    {
        int code = tid & 31;
        int rq = tid >> 5;               // 8 groups of 32 rows
        float asum = 0.f;
        float* dst = g_aw + ((size_t)b * NPIX + n0) * KCODES + code;
#pragma unroll
        for (int rr = 0; rr < 32; rr++) {
            int r = rq * 32 + rr;
            float v = aw_s[r * AWSTR + code];
            asum += v;
            dst[(size_t)r * KCODES] = v;
        }
        atomicAdd(&aws_s[code], asum);
    }
    __syncthreads();
    if (tid < 32) atomicAdd(&g_awsum[b * KCODES + tid], aws_s[tid]);
}

// ---------------- K2b: enc aggregation GEMM: enc += aw^T @ feat ----------------
// Block: (b, cblk of 128 ch, 1/8 of pixels). 4 warps, out tile [32 x 128].
#define FSTR 136
#define WSTR 40
__global__ __launch_bounds__(128) void k_agg()
{
    extern __shared__ float as[];
    float* feat_s = as;                    // 128 x 136
    float* aw_s   = as + 128 * FSTR;       // 128 x 40

    const int tid  = threadIdx.x;
    const int wid  = tid >> 5;
    const int lane = tid & 31;
    const int g    = lane >> 2;
    const int tg   = lane & 3;

    const int b    = blockIdx.x >> 5;
    const int cblk = (blockIdx.x >> 3) & 3;
    const int sch  = blockIdx.x & 7;
    const int c0   = cblk * 128;
    const int n0   = sch * 2048;
    const int wc0  = wid * 32;

    const float* fb = g_feat + ((size_t)b * NPIX + n0) * CCH + c0;
    const float* ab = g_aw + ((size_t)b * NPIX + n0) * KCODES;

    float c[2][4][4];
#pragma unroll
    for (int i = 0; i < 2; i++)
#pragma unroll
        for (int j = 0; j < 4; j++)
#pragma unroll
            for (int r = 0; r < 4; r++) c[i][j][r] = 0.f;

    const int frow = tid >> 5;     // 0..3
    const int fcol = tid & 31;
    const int arow = tid >> 3;     // 0..15
    const int acol = tid & 7;

    for (int ch = 0; ch < 16; ch++) {
        {
            uint32_t fd = smem_u32(feat_s);
            const float* fsrc = fb + (size_t)(ch * 128) * CCH + fcol * 4;
#pragma unroll
            for (int jj = 0; jj < 32; jj++) {
                int r = frow + 4 * jj;
                CP16(fd + r * (FSTR * 4) + fcol * 16, fsrc + (size_t)r * CCH);
            }
            uint32_t ad = smem_u32(aw_s);
            const float* asrc = ab + (size_t)(ch * 128) * KCODES + acol * 4;
#pragma unroll
            for (int jj = 0; jj < 8; jj++) {
                int r = arow + 16 * jj;
                CP16(ad + r * (WSTR * 4) + acol * 16, asrc + (size_t)r * KCODES);
            }
            CPCOMMIT();
            CPWAIT0();
            __syncthreads();
        }

        const unsigned* F = (const unsigned*)feat_s;
        const unsigned* A = (const unsigned*)aw_s;
#pragma unroll
        for (int k8 = 0; k8 < 16; k8++) {
            const int kb = k8 * 8;
            unsigned af[2][4];
#pragma unroll
            for (int i = 0; i < 2; i++) {
                int m = i * 16 + g;
                af[i][0] = A[(kb + tg) * WSTR + m];
                af[i][1] = A[(kb + tg) * WSTR + m + 8];
                af[i][2] = A[(kb + tg + 4) * WSTR + m];
                af[i][3] = A[(kb + tg + 4) * WSTR + m + 8];
            }
            unsigned bf[4][2];
#pragma unroll
            for (int j = 0; j < 4; j++) {
                int n = wc0 + j * 8 + g;
                bf[j][0] = F[(kb + tg) * FSTR + n];
                bf[j][1] = F[(kb + tg + 4) * FSTR + n];
            }
#pragma unroll
            for (int i = 0; i < 2; i++)
#pragma unroll
                for (int j = 0; j < 4; j++)
                    mma_tf32(c[i][j], af[i], bf[j]);
        }
        __syncthreads();
    }

    // epilogue: atomic add to g_enc[b][code][c]
#pragma unroll
    for (int i = 0; i < 2; i++) {
        int code0 = i * 16 + g;
        float* e0 = g_enc + ((size_t)b * KCODES + code0) * CCH + c0 + wc0;
        float* e1 = e0 + (size_t)8 * CCH;
#pragma unroll
        for (int j = 0; j < 4; j++) {
            int nl = j * 8 + 2 * tg;
            atomicAdd(e0 + nl,     c[i][j][0]);
            atomicAdd(e0 + nl + 1, c[i][j][1]);
            atomicAdd(e1 + nl,     c[i][j][2]);
            atomicAdd(e1 + nl + 1, c[i][j][3]);
        }
    }
}

// ---------------- K3: finalize enc -> BN1 + ReLU + mean over codes ----------
__global__ void k_final(const float* __restrict__ cw,
                        const float* __restrict__ g1, const float* __restrict__ b1,
                        const float* __restrict__ m1, const float* __restrict__ v1,
                        float* __restrict__ out)
{
    int b = blockIdx.x;
    int c = threadIdx.x;
    float sum = 0.f;
#pragma unroll
    for (int k = 0; k < KCODES; k++) {
        float e = g_enc[(b * KCODES + k) * CCH + c] - g_awsum[b * KCODES + k] * cw[k * CCH + c];
        float s = g1[k] * rsqrtf(v1[k] + EPS);
        e = (e - m1[k]) * s + b1[k];
        sum += fmaxf(e, 0.f);
    }
    float ef = sum * (1.f / (float)KCODES);
    g_encfeat[b * CCH + c] = ef;
    out[b * CCH + c] = ef;
}

// ---------------- K4: fc + sigmoid -> 1+gamma --------------------------------
__global__ void k_fc(const float* __restrict__ fcw, const float* __restrict__ fcb)
{
    int w = blockIdx.x * 8 + (threadIdx.x >> 5);
    int lane = threadIdx.x & 31;
    int b = w >> 9, co = w & 511;
    const float* wr = fcw + (size_t)co * CCH;
    const float* ef = g_encfeat + b * CCH;
    float s = 0.f;
#pragma unroll
    for (int j = 0; j < 16; j++) s += wr[lane + 32 * j] * ef[lane + 32 * j];
    s += __shfl_xor_sync(~0u, s, 16);
    s += __shfl_xor_sync(~0u, s, 8);
    s += __shfl_xor_sync(~0u, s, 4);
    s += __shfl_xor_sync(~0u, s, 2);
    s += __shfl_xor_sync(~0u, s, 1);
    if (lane == 0)
        g_gamma1p[w] = 1.f + 1.f / (1.f + __expf(-(s + fcb[co])));
}

// ---------------- K5: output = relu(x * (1+gamma)) ---------------------------
__global__ void k_out(const float4* __restrict__ x4, float4* __restrict__ o4, int n4)
{
    int i = blockIdx.x * blockDim.x + threadIdx.x;
    if (i >= n4) return;
    float g = g_gamma1p[i >> 12];
    float4 v = x4[i];
    v.x = fmaxf(v.x * g, 0.f);
    v.y = fmaxf(v.y * g, 0.f);
    v.z = fmaxf(v.z * g, 0.f);
    v.w = fmaxf(v.w * g, 0.f);
    o4[i] = v;
}

// ---------------- launch -----------------------------------------------------
extern "C" void kernel_launch(void* const* d_in, const int* in_sizes, int n_in,
                              void* d_out, int out_size)
{
    const float* x    = (const float*)d_in[0];
    const float* cwn  = (const float*)d_in[1];
    const float* b2g  = (const float*)d_in[2];
    const float* b2b  = (const float*)d_in[3];
    const float* b2m  = (const float*)d_in[4];
    const float* b2v  = (const float*)d_in[5];
    const float* cw   = (const float*)d_in[6];
    const float* sc   = (const float*)d_in[7];
    const float* b1g  = (const float*)d_in[8];
    const float* b1b  = (const float*)d_in[9];
    const float* b1m  = (const float*)d_in[10];
    const float* b1v  = (const float*)d_in[11];
    const float* fcw  = (const float*)d_in[12];
    const float* fcb  = (const float*)d_in[13];
    float* out = (float*)d_out;

    const int conv_smem = (2 * ATILE + 2 * BTILE) * 4;
    cudaFuncSetAttribute(k_conv_mma, cudaFuncAttributeMaxDynamicSharedMemorySize,
                         conv_smem);
    const int logits_smem = (2 * 256 * LSTR + 32 * CWSTR + 256 * AWSTR + 32 + 32 + 256 + 32) * 4;
    cudaFuncSetAttribute(k_logits, cudaFuncAttributeMaxDynamicSharedMemorySize,
                         logits_smem);
    const int agg_smem = (128 * FSTR + 128 * WSTR) * 4;
    cudaFuncSetAttribute(k_agg, cudaFuncAttributeMaxDynamicSharedMemorySize,
                         agg_smem);

    k_zero<<<(BX * KCODES * CCH + 255) / 256, 256>>>();

    k_pre<<<(int)((NX4 + NW4 + NC4 + 255) / 256), 256>>>(
        (const float4*)x, (const float4*)cwn, (const float4*)cw);

    k_c2<<<1, 1024>>>(cw);

    dim3 g1(NPIX / 128, CCH / 128, BX);
    k_conv_mma<<<g1, 256, conv_smem>>>(b2g, b2b, b2m, b2v);

    k_logits<<<BX * (NPIX / 256), 256, logits_smem>>>(sc);

    k_agg<<<BX * 4 * 8, 128, agg_smem>>>();

    k_final<<<BX, CCH>>>(cw, b1g, b1b, b1m, b1v, out);

    k_fc<<<BX * CCH / 8, 256>>>(fcw, fcb);

    int n4 = BX * CCH * NPIX / 4;
    k_out<<<n4 / 256, 256>>>((const float4*)x, (float4*)(out + BX * CCH), n4);
}